// round 15
// baseline (speedup 1.0000x reference)
#include <cuda_runtime.h>
#include <cuda_bf16.h>
#include <cstdint>

#define N_NODES 100000
#define N_EDGES 1600000

// ---- scratch (device globals: no allocation allowed) ----
__device__ int   g_cnt [N_NODES];
__device__ int   g_off [N_NODES];
__device__ int   g_cur [N_NODES];
__device__ int   g_ssrc[N_EDGES];
__device__ float g_h1  [(size_t)N_NODES * 128];
__device__ __nv_bfloat16 g_h1b[(size_t)N_NODES * 128];
__device__ float g_agg2[(size_t)N_NODES * 128];
__device__ float g_pool[128];

__device__ __forceinline__ uint32_t cvt_tf32_rna(float f) {
    uint32_t r;
    asm("cvt.rna.tf32.f32 %0, %1;" : "=r"(r) : "f"(f));
    return r;
}

// m16n8k8 tf32 HMMA, fp32 accumulate (sm_80+, valid on plain sm_103 target)
__device__ __forceinline__ void mma_tf32(float* c,
                                         uint32_t a0, uint32_t a1, uint32_t a2, uint32_t a3,
                                         uint32_t b0, uint32_t b1) {
    asm volatile(
        "mma.sync.aligned.m16n8k8.row.col.f32.tf32.tf32.f32 "
        "{%0,%1,%2,%3}, {%4,%5,%6,%7}, {%8,%9}, {%0,%1,%2,%3};"
        : "+f"(c[0]), "+f"(c[1]), "+f"(c[2]), "+f"(c[3])
        : "r"(a0), "r"(a1), "r"(a2), "r"(a3), "r"(b0), "r"(b1));
}

// ---------------------------------------------------------------------------
// 1) init: zero histogram + pool accumulator
__global__ void k_init() {
    int i = blockIdx.x * blockDim.x + threadIdx.x;
    if (i < N_NODES) g_cnt[i] = 0;
    if (i < 128)     g_pool[i] = 0.f;
}

// 2) histogram of dst
__global__ void k_hist(const int* __restrict__ ei) {
    int e = blockIdx.x * blockDim.x + threadIdx.x;
    if (e < N_EDGES) atomicAdd(&g_cnt[ei[N_EDGES + e]], 1);
}

// 3) single-block exclusive scan of g_cnt -> g_off (and copy to g_cur)
__global__ void k_scan() {
    __shared__ int wsum[32];
    int t = threadIdx.x, lane = t & 31, w = t >> 5;
    int carry = 0;
    for (int base = 0; base < N_NODES; base += 1024) {
        int i = base + t;
        int v = (i < N_NODES) ? g_cnt[i] : 0;
        int xv = v;
        #pragma unroll
        for (int d = 1; d < 32; d <<= 1) {
            int y = __shfl_up_sync(0xffffffffu, xv, d);
            if (lane >= d) xv += y;
        }
        if (lane == 31) wsum[w] = xv;
        __syncthreads();
        if (w == 0) {
            int y = wsum[lane];
            #pragma unroll
            for (int d = 1; d < 32; d <<= 1) {
                int z = __shfl_up_sync(0xffffffffu, y, d);
                if (lane >= d) y += z;
            }
            wsum[lane] = y;
        }
        __syncthreads();
        int excl = xv - v + (w > 0 ? wsum[w - 1] : 0) + carry;
        if (i < N_NODES) { g_off[i] = excl; g_cur[i] = excl; }
        carry += wsum[31];
        __syncthreads();
    }
}

// 4) scatter src indices into dst-sorted order (counting sort)
__global__ void k_scatter(const int* __restrict__ ei) {
    int e = blockIdx.x * blockDim.x + threadIdx.x;
    if (e < N_EDGES) {
        int d = ei[N_EDGES + e];
        int p = atomicAdd(&g_cur[d], 1);
        g_ssrc[p] = ei[e];
    }
}

// 5) layer 1 fused: CSR-aggregate x (4-dim) + h1 = relu(agg@W1_rel^T + b1 + x@W1_root^T)
//    writes h1 in fp32 (for GEMM root branch) AND bf16 (for the agg2 gather).
__global__ void k_h1(const float* __restrict__ x,
                     const float* __restrict__ W1_rel,
                     const float* __restrict__ b1,
                     const float* __restrict__ W1_root) {
    __shared__ float sWr[512], sWo[512], sb[128];
    int t = threadIdx.x;  // 128 threads
    sb[t] = b1[t];
    #pragma unroll
    for (int r = 0; r < 4; r++) {
        sWr[t + 128 * r] = W1_rel[t + 128 * r];
        sWo[t + 128 * r] = W1_root[t + 128 * r];
    }
    __syncthreads();
    int n = blockIdx.x * 128 + t;
    if (n >= N_NODES) return;

    const float4* x4 = (const float4*)x;
    float4 xi = x4[n];
    float4 ag = make_float4(0.f, 0.f, 0.f, 0.f);
    int s0 = g_off[n], c = g_cnt[n];
    for (int i = 0; i < c; i++) {
        int s = g_ssrc[s0 + i];
        float4 v = x4[s];
        ag.x += v.x; ag.y += v.y; ag.z += v.z; ag.w += v.w;
    }
    float4* out = (float4*)(g_h1 + (size_t)n * 128);
    uint2*  outb = (uint2*)(g_h1b + (size_t)n * 128);
    #pragma unroll
    for (int j4 = 0; j4 < 32; j4++) {
        float o[4];
        #pragma unroll
        for (int u = 0; u < 4; u++) {
            int j = j4 * 4 + u;
            float v = sb[j];
            v += ag.x * sWr[j * 4 + 0] + ag.y * sWr[j * 4 + 1]
               + ag.z * sWr[j * 4 + 2] + ag.w * sWr[j * 4 + 3];
            v += xi.x * sWo[j * 4 + 0] + xi.y * sWo[j * 4 + 1]
               + xi.z * sWo[j * 4 + 2] + xi.w * sWo[j * 4 + 3];
            o[u] = fmaxf(v, 0.f);
        }
        out[j4] = make_float4(o[0], o[1], o[2], o[3]);
        __nv_bfloat162 p0 = __floats2bfloat162_rn(o[0], o[1]);
        __nv_bfloat162 p1 = __floats2bfloat162_rn(o[2], o[3]);
        uint2 pk;
        pk.x = *(uint32_t*)&p0;
        pk.y = *(uint32_t*)&p1;
        outb[j4] = pk;
    }
}

// 6) layer 2 aggregation: warp per node, bf16 gather (half the bytes of fp32),
//    fp32 accumulate, 2 independent edge-rows in flight per iteration.
__global__ void k_agg2() {
    int gtid = blockIdx.x * blockDim.x + threadIdx.x;
    int node = gtid >> 5;
    int lane = gtid & 31;
    if (node >= N_NODES) return;
    int s0 = g_off[node], c = g_cnt[node];
    const uint2* h1b = (const uint2*)g_h1b;   // 32 uint2 per row (128 bf16)
    float a0 = 0.f, a1 = 0.f, a2 = 0.f, a3 = 0.f;
    float b0 = 0.f, b1 = 0.f, b2 = 0.f, b3 = 0.f;
    int i = 0;
    for (; i + 2 <= c; i += 2) {
        int sA = g_ssrc[s0 + i];
        int sB = g_ssrc[s0 + i + 1];
        uint2 vA = h1b[(size_t)sA * 32 + lane];   // two independent loads in flight
        uint2 vB = h1b[(size_t)sB * 32 + lane];
        float2 fA0 = __bfloat1622float2(*(__nv_bfloat162*)&vA.x);
        float2 fA1 = __bfloat1622float2(*(__nv_bfloat162*)&vA.y);
        a0 += fA0.x; a1 += fA0.y; a2 += fA1.x; a3 += fA1.y;
        float2 fB0 = __bfloat1622float2(*(__nv_bfloat162*)&vB.x);
        float2 fB1 = __bfloat1622float2(*(__nv_bfloat162*)&vB.y);
        b0 += fB0.x; b1 += fB0.y; b2 += fB1.x; b3 += fB1.y;
    }
    if (i < c) {
        int s = g_ssrc[s0 + i];
        uint2 v = h1b[(size_t)s * 32 + lane];
        float2 f0 = __bfloat1622float2(*(__nv_bfloat162*)&v.x);
        float2 f1 = __bfloat1622float2(*(__nv_bfloat162*)&v.y);
        a0 += f0.x; a1 += f0.y; a2 += f1.x; a3 += f1.y;
    }
    ((float4*)g_agg2)[(size_t)node * 32 + lane] =
        make_float4(a0 + b0, a1 + b1, a2 + b2, a3 + b3);
}

// ---------------------------------------------------------------------------
// 7) layer-2 GEMM on mma.sync tf32 with fused bias+relu+mean-pool.
//    (R9-winning form: no register prefetch — avoids spills at occ 2.)
#define PAD 36   // 32 + 4 word padding: conflict-free fragment LDS
__global__ __launch_bounds__(256, 2) void k_gemm_mma(const float* __restrict__ W2_rel,
                                                     const float* __restrict__ W2_root,
                                                     const float* __restrict__ b2) {
    __shared__ uint32_t As[128][PAD];
    __shared__ uint32_t Bs[128][PAD];
    __shared__ float sb2s[128];
    __shared__ float spool[128];

    int t = threadIdx.x;
    int lane = t & 31, wid = t >> 5;
    int gid = lane >> 2, tg = lane & 3;      // mma fragment coords
    int warp_m = wid & 1, warp_n = wid >> 1; // 2 x 4 warp grid
    int block_m = blockIdx.x * 128;

    if (t < 128) { sb2s[t] = b2[t]; spool[t] = 0.f; }

    float c[4][4][4];  // [m_sub][n_sub][reg]
    #pragma unroll
    for (int mt = 0; mt < 4; mt++)
        #pragma unroll
        for (int nt = 0; nt < 4; nt++)
            #pragma unroll
            for (int r = 0; r < 4; r++) c[mt][nt][r] = 0.f;

    int rr = t >> 3;          // 0..31 row within 32-row group
    int cc = (t & 7) * 4;     // word col 0,4,...,28

    #pragma unroll 1
    for (int kc = 0; kc < 8; kc++) {
        const float* Asrc = (kc < 4) ? g_agg2 : g_h1;
        const float* Bsrc = (kc < 4) ? W2_rel : W2_root;
        int kbase = (kc & 3) * 32;

        __syncthreads();   // previous chunk's mma done reading SMEM
        #pragma unroll
        for (int i = 0; i < 4; i++) {
            int row = rr + i * 32;
            int gmr = block_m + row;
            if (gmr >= N_NODES) gmr = N_NODES - 1;   // clamp; masked in epilogue
            float4 va = *(const float4*)(Asrc + (size_t)gmr * 128 + kbase + cc);
            As[row][cc + 0] = cvt_tf32_rna(va.x);
            As[row][cc + 1] = cvt_tf32_rna(va.y);
            As[row][cc + 2] = cvt_tf32_rna(va.z);
            As[row][cc + 3] = cvt_tf32_rna(va.w);
            float4 vb = *(const float4*)(Bsrc + (size_t)row * 128 + kbase + cc);
            Bs[row][cc + 0] = cvt_tf32_rna(vb.x);
            Bs[row][cc + 1] = cvt_tf32_rna(vb.y);
            Bs[row][cc + 2] = cvt_tf32_rna(vb.z);
            Bs[row][cc + 3] = cvt_tf32_rna(vb.w);
        }
        __syncthreads();

        #pragma unroll
        for (int ks = 0; ks < 4; ks++) {
            int k0 = ks * 8;
            uint32_t bf[4][2];
            #pragma unroll
            for (int nt = 0; nt < 4; nt++) {
                int col = warp_n * 32 + nt * 8 + gid;
                bf[nt][0] = Bs[col][k0 + tg];
                bf[nt][1] = Bs[col][k0 + tg + 4];
            }
            #pragma unroll
            for (int mt = 0; mt < 4; mt++) {
                int row = warp_m * 64 + mt * 16 + gid;
                uint32_t a0 = As[row][k0 + tg];
                uint32_t a1 = As[row + 8][k0 + tg];
                uint32_t a2 = As[row][k0 + tg + 4];
                uint32_t a3 = As[row + 8][k0 + tg + 4];
                #pragma unroll
                for (int nt = 0; nt < 4; nt++)
                    mma_tf32(c[mt][nt], a0, a1, a2, a3, bf[nt][0], bf[nt][1]);
            }
        }
    }

    // epilogue: bias + relu + mask invalid rows, column-sum into spool
    #pragma unroll
    for (int nt = 0; nt < 4; nt++) {
        int colg = warp_n * 32 + nt * 8 + tg * 2;
        float bias0 = sb2s[colg], bias1 = sb2s[colg + 1];
        float ps0 = 0.f, ps1 = 0.f;
        #pragma unroll
        for (int mt = 0; mt < 4; mt++) {
            int rowg = block_m + warp_m * 64 + mt * 16 + gid;
            bool v0 = rowg < N_NODES;
            bool v1 = (rowg + 8) < N_NODES;
            float e0 = fmaxf(c[mt][nt][0] + bias0, 0.f);
            float e1 = fmaxf(c[mt][nt][1] + bias1, 0.f);
            float e2 = fmaxf(c[mt][nt][2] + bias0, 0.f);
            float e3 = fmaxf(c[mt][nt][3] + bias1, 0.f);
            ps0 += (v0 ? e0 : 0.f) + (v1 ? e2 : 0.f);
            ps1 += (v0 ? e1 : 0.f) + (v1 ? e3 : 0.f);
        }
        // reduce over gid (lane bits 2..4)
        #pragma unroll
        for (int d = 4; d < 32; d <<= 1) {
            ps0 += __shfl_xor_sync(0xffffffffu, ps0, d);
            ps1 += __shfl_xor_sync(0xffffffffu, ps1, d);
        }
        if (lane < 4) {
            atomicAdd(&spool[colg], ps0);
            atomicAdd(&spool[colg + 1], ps1);
        }
    }
    __syncthreads();
    if (t < 128) atomicAdd(&g_pool[t], spool[t]);
}

// 8) final head: out = (pool/N) @ Wlin^T + blin
__global__ void k_final(const float* __restrict__ Wlin,
                        const float* __restrict__ blin,
                        float* __restrict__ out) {
    __shared__ float s0[128], s1[128];
    int l = threadIdx.x;  // 128 threads
    float g = g_pool[l] * (1.0f / (float)N_NODES);
    s0[l] = g * Wlin[l];
    s1[l] = g * Wlin[128 + l];
    __syncthreads();
    for (int st = 64; st > 0; st >>= 1) {
        if (l < st) { s0[l] += s0[l + st]; s1[l] += s1[l + st]; }
        __syncthreads();
    }
    if (l == 0) {
        out[0] = s0[0] + blin[0];
        out[1] = s1[0] + blin[1];
    }
}

// ---------------------------------------------------------------------------
extern "C" void kernel_launch(void* const* d_in, const int* in_sizes, int n_in,
                              void* d_out, int out_size) {
    const float* x       = (const float*)d_in[0];
    const int*   ei      = (const int*)  d_in[1];
    const float* W1_rel  = (const float*)d_in[2];
    const float* b1      = (const float*)d_in[3];
    const float* W1_root = (const float*)d_in[4];
    const float* W2_rel  = (const float*)d_in[5];
    const float* b2      = (const float*)d_in[6];
    const float* W2_root = (const float*)d_in[7];
    const float* Wlin    = (const float*)d_in[8];
    const float* blin    = (const float*)d_in[9];
    float* out = (float*)d_out;

    k_init    <<<(N_NODES + 255) / 256, 256>>>();
    k_hist    <<<(N_EDGES + 255) / 256, 256>>>(ei);
    k_scan    <<<1, 1024>>>();
    k_scatter <<<(N_EDGES + 255) / 256, 256>>>(ei);
    k_h1      <<<(N_NODES + 127) / 128, 128>>>(x, W1_rel, b1, W1_root);
    k_agg2    <<<(N_NODES * 32 + 255) / 256, 256>>>();
    k_gemm_mma<<<(N_NODES + 127) / 128, 256>>>(W2_rel, W2_root, b2);
    k_final   <<<1, 128>>>(Wlin, blin, out);
}

// round 16
// speedup vs baseline: 1.1299x; 1.1299x over previous
#include <cuda_runtime.h>
#include <cuda_bf16.h>
#include <cstdint>

#define N_NODES 100000
#define N_EDGES 1600000
#define NSCANB  98          // ceil(N_NODES/1024)

// ---- scratch (device globals: no allocation allowed) ----
__device__ int   g_cnt [N_NODES];
__device__ int   g_off [N_NODES];
__device__ int   g_cur [N_NODES];
__device__ int   g_ssrc[N_EDGES];
__device__ int   g_bsum[NSCANB];
__device__ int   g_bpre[NSCANB];
__device__ float g_h1  [(size_t)N_NODES * 128];
__device__ float g_agg2[(size_t)N_NODES * 128];
__device__ float g_pool[128];

__device__ __forceinline__ uint32_t cvt_tf32_rna(float f) {
    uint32_t r;
    asm("cvt.rna.tf32.f32 %0, %1;" : "=r"(r) : "f"(f));
    return r;
}

// m16n8k8 tf32 HMMA, fp32 accumulate (sm_80+, valid on plain sm_103 target)
__device__ __forceinline__ void mma_tf32(float* c,
                                         uint32_t a0, uint32_t a1, uint32_t a2, uint32_t a3,
                                         uint32_t b0, uint32_t b1) {
    asm volatile(
        "mma.sync.aligned.m16n8k8.row.col.f32.tf32.tf32.f32 "
        "{%0,%1,%2,%3}, {%4,%5,%6,%7}, {%8,%9}, {%0,%1,%2,%3};"
        : "+f"(c[0]), "+f"(c[1]), "+f"(c[2]), "+f"(c[3])
        : "r"(a0), "r"(a1), "r"(a2), "r"(a3), "r"(b0), "r"(b1));
}

// ---------------------------------------------------------------------------
// 1) init: zero histogram + pool accumulator
__global__ void k_init() {
    int i = blockIdx.x * blockDim.x + threadIdx.x;
    if (i < N_NODES) g_cnt[i] = 0;
    if (i < 128)     g_pool[i] = 0.f;
}

// 2) histogram of dst
__global__ void k_hist(const int* __restrict__ ei) {
    int e = blockIdx.x * blockDim.x + threadIdx.x;
    if (e < N_EDGES) atomicAdd(&g_cnt[ei[N_EDGES + e]], 1);
}

// 3a) per-block exclusive scan of 1024 g_cnt elements; block totals -> g_bsum
__global__ void k_scan1() {
    __shared__ int wsum[32];
    int t = threadIdx.x, lane = t & 31, w = t >> 5;
    int i = blockIdx.x * 1024 + t;
    int v = (i < N_NODES) ? g_cnt[i] : 0;
    int xv = v;
    #pragma unroll
    for (int d = 1; d < 32; d <<= 1) {
        int y = __shfl_up_sync(0xffffffffu, xv, d);
        if (lane >= d) xv += y;
    }
    if (lane == 31) wsum[w] = xv;
    __syncthreads();
    if (w == 0) {
        int y = wsum[lane];
        #pragma unroll
        for (int d = 1; d < 32; d <<= 1) {
            int z = __shfl_up_sync(0xffffffffu, y, d);
            if (lane >= d) y += z;
        }
        wsum[lane] = y;
    }
    __syncthreads();
    int excl = xv - v + (w > 0 ? wsum[w - 1] : 0);
    if (i < N_NODES) g_off[i] = excl;
    if (t == 1023)   g_bsum[blockIdx.x] = excl + v;
}

// 3b) single small block scans the 98 block totals
__global__ void k_scan2() {
    __shared__ int ws[4];
    int t = threadIdx.x, lane = t & 31, w = t >> 5;   // 128 threads
    int v = (t < NSCANB) ? g_bsum[t] : 0;
    int xv = v;
    #pragma unroll
    for (int d = 1; d < 32; d <<= 1) {
        int y = __shfl_up_sync(0xffffffffu, xv, d);
        if (lane >= d) xv += y;
    }
    if (lane == 31) ws[w] = xv;
    __syncthreads();
    int add = 0;
    #pragma unroll
    for (int k = 0; k < 4; k++) if (k < w) add += ws[k];
    if (t < NSCANB) g_bpre[t] = xv - v + add;
}

// 3c) add block prefix; materialize g_off and g_cur
__global__ void k_scan3() {
    int i = blockIdx.x * 1024 + threadIdx.x;
    if (i < N_NODES) {
        int o = g_off[i] + g_bpre[blockIdx.x];
        g_off[i] = o;
        g_cur[i] = o;
    }
}

// 4) scatter src indices into dst-sorted order (counting sort)
__global__ void k_scatter(const int* __restrict__ ei) {
    int e = blockIdx.x * blockDim.x + threadIdx.x;
    if (e < N_EDGES) {
        int d = ei[N_EDGES + e];
        int p = atomicAdd(&g_cur[d], 1);
        g_ssrc[p] = ei[e];
    }
}

// 5) layer 1 fused: CSR-aggregate x (4-dim) + h1 = relu(agg@W1_rel^T + b1 + x@W1_root^T)
//    4 threads per node (gather split 4-way, shfl-combined); outputs staged in
//    SMEM and written to g_h1 fully coalesced (512B contiguous per row).
__global__ __launch_bounds__(128) void k_h1(const float* __restrict__ x,
                     const float* __restrict__ W1_rel,
                     const float* __restrict__ b1,
                     const float* __restrict__ W1_root) {
    __shared__ float sWr[512], sWo[512], sb[128];
    __shared__ float hs[32 * 132];   // 32 rows x (4 quarters x 33 floats)
    int t = threadIdx.x;  // 128 threads
    sb[t] = b1[t];
    #pragma unroll
    for (int r = 0; r < 4; r++) {
        sWr[t + 128 * r] = W1_rel[t + 128 * r];
        sWo[t + 128 * r] = W1_root[t + 128 * r];
    }
    __syncthreads();

    int q = t & 3, rloc = t >> 2;          // 4 threads per row, 32 rows per pass
    int qq = t >> 5, jj2 = t & 31;         // coalesced-store coords (j_logical = t)
    const float4* x4 = (const float4*)x;

    #pragma unroll 1
    for (int it = 0; it < 4; it++) {
        int n = blockIdx.x * 128 + it * 32 + rloc;
        float4 ag = make_float4(0.f, 0.f, 0.f, 0.f);
        float4 xi = make_float4(0.f, 0.f, 0.f, 0.f);
        if (n < N_NODES) {
            xi = x4[n];
            int s0 = g_off[n], c = g_cnt[n];
            for (int i = q; i < c; i += 4) {   // 4-way parallel gather
                int s = g_ssrc[s0 + i];
                float4 v = x4[s];
                ag.x += v.x; ag.y += v.y; ag.z += v.z; ag.w += v.w;
            }
        }
        // combine partial sums across the 4-thread group
        #pragma unroll
        for (int d = 1; d < 4; d <<= 1) {
            ag.x += __shfl_xor_sync(0xffffffffu, ag.x, d);
            ag.y += __shfl_xor_sync(0xffffffffu, ag.y, d);
            ag.z += __shfl_xor_sync(0xffffffffu, ag.z, d);
            ag.w += __shfl_xor_sync(0xffffffffu, ag.w, d);
        }
        // each thread computes its 32-column quarter, staged in SMEM
        if (n < N_NODES) {
            #pragma unroll
            for (int jj = 0; jj < 32; jj++) {
                int j = q * 32 + jj;
                float v = sb[j];
                v += ag.x * sWr[j * 4 + 0] + ag.y * sWr[j * 4 + 1]
                   + ag.z * sWr[j * 4 + 2] + ag.w * sWr[j * 4 + 3];
                v += xi.x * sWo[j * 4 + 0] + xi.y * sWo[j * 4 + 1]
                   + xi.z * sWo[j * 4 + 2] + xi.w * sWo[j * 4 + 3];
                hs[rloc * 132 + q * 33 + jj] = fmaxf(v, 0.f);
            }
        }
        __syncthreads();
        // coalesced store: per row, 128 threads write 512B contiguous
        int rbase = blockIdx.x * 128 + it * 32;
        #pragma unroll 4
        for (int r = 0; r < 32; r++) {
            int nr = rbase + r;
            if (nr < N_NODES)
                g_h1[(size_t)nr * 128 + t] = hs[r * 132 + qq * 33 + jj2];
        }
        __syncthreads();
    }
}

// 6) layer 2 aggregation: warp per node, atomic-free CSR sum of h1 rows (fp32)
__global__ void k_agg2() {
    int gtid = blockIdx.x * blockDim.x + threadIdx.x;
    int node = gtid >> 5;
    int lane = gtid & 31;
    if (node >= N_NODES) return;
    int s0 = g_off[node], c = g_cnt[node];
    const float4* h1v = (const float4*)g_h1;
    float4 acc = make_float4(0.f, 0.f, 0.f, 0.f);
    for (int i = 0; i < c; i++) {
        int s = g_ssrc[s0 + i];               // broadcast load across warp
        float4 v = h1v[(size_t)s * 32 + lane];
        acc.x += v.x; acc.y += v.y; acc.z += v.z; acc.w += v.w;
    }
    ((float4*)g_agg2)[(size_t)node * 32 + lane] = acc;
}

// ---------------------------------------------------------------------------
// 7) layer-2 GEMM on mma.sync tf32 with fused bias+relu+mean-pool (R9 form).
#define PAD 36   // 32 + 4 word padding: conflict-free fragment LDS
__global__ __launch_bounds__(256, 2) void k_gemm_mma(const float* __restrict__ W2_rel,
                                                     const float* __restrict__ W2_root,
                                                     const float* __restrict__ b2) {
    __shared__ uint32_t As[128][PAD];
    __shared__ uint32_t Bs[128][PAD];
    __shared__ float sb2s[128];
    __shared__ float spool[128];

    int t = threadIdx.x;
    int lane = t & 31, wid = t >> 5;
    int gid = lane >> 2, tg = lane & 3;      // mma fragment coords
    int warp_m = wid & 1, warp_n = wid >> 1; // 2 x 4 warp grid
    int block_m = blockIdx.x * 128;

    if (t < 128) { sb2s[t] = b2[t]; spool[t] = 0.f; }

    float c[4][4][4];  // [m_sub][n_sub][reg]
    #pragma unroll
    for (int mt = 0; mt < 4; mt++)
        #pragma unroll
        for (int nt = 0; nt < 4; nt++)
            #pragma unroll
            for (int r = 0; r < 4; r++) c[mt][nt][r] = 0.f;

    int rr = t >> 3;          // 0..31 row within 32-row group
    int cc = (t & 7) * 4;     // word col 0,4,...,28

    #pragma unroll 1
    for (int kc = 0; kc < 8; kc++) {
        const float* Asrc = (kc < 4) ? g_agg2 : g_h1;
        const float* Bsrc = (kc < 4) ? W2_rel : W2_root;
        int kbase = (kc & 3) * 32;

        __syncthreads();   // previous chunk's mma done reading SMEM
        #pragma unroll
        for (int i = 0; i < 4; i++) {
            int row = rr + i * 32;
            int gmr = block_m + row;
            if (gmr >= N_NODES) gmr = N_NODES - 1;   // clamp; masked in epilogue
            float4 va = *(const float4*)(Asrc + (size_t)gmr * 128 + kbase + cc);
            As[row][cc + 0] = cvt_tf32_rna(va.x);
            As[row][cc + 1] = cvt_tf32_rna(va.y);
            As[row][cc + 2] = cvt_tf32_rna(va.z);
            As[row][cc + 3] = cvt_tf32_rna(va.w);
            float4 vb = *(const float4*)(Bsrc + (size_t)row * 128 + kbase + cc);
            Bs[row][cc + 0] = cvt_tf32_rna(vb.x);
            Bs[row][cc + 1] = cvt_tf32_rna(vb.y);
            Bs[row][cc + 2] = cvt_tf32_rna(vb.z);
            Bs[row][cc + 3] = cvt_tf32_rna(vb.w);
        }
        __syncthreads();

        #pragma unroll
        for (int ks = 0; ks < 4; ks++) {
            int k0 = ks * 8;
            uint32_t bf[4][2];
            #pragma unroll
            for (int nt = 0; nt < 4; nt++) {
                int col = warp_n * 32 + nt * 8 + gid;
                bf[nt][0] = Bs[col][k0 + tg];
                bf[nt][1] = Bs[col][k0 + tg + 4];
            }
            #pragma unroll
            for (int mt = 0; mt < 4; mt++) {
                int row = warp_m * 64 + mt * 16 + gid;
                uint32_t a0 = As[row][k0 + tg];
                uint32_t a1 = As[row + 8][k0 + tg];
                uint32_t a2 = As[row][k0 + tg + 4];
                uint32_t a3 = As[row + 8][k0 + tg + 4];
                #pragma unroll
                for (int nt = 0; nt < 4; nt++)
                    mma_tf32(c[mt][nt], a0, a1, a2, a3, bf[nt][0], bf[nt][1]);
            }
        }
    }

    // epilogue: bias + relu + mask invalid rows, column-sum into spool
    #pragma unroll
    for (int nt = 0; nt < 4; nt++) {
        int colg = warp_n * 32 + nt * 8 + tg * 2;
        float bias0 = sb2s[colg], bias1 = sb2s[colg + 1];
        float ps0 = 0.f, ps1 = 0.f;
        #pragma unroll
        for (int mt = 0; mt < 4; mt++) {
            int rowg = block_m + warp_m * 64 + mt * 16 + gid;
            bool v0 = rowg < N_NODES;
            bool v1 = (rowg + 8) < N_NODES;
            float e0 = fmaxf(c[mt][nt][0] + bias0, 0.f);
            float e1 = fmaxf(c[mt][nt][1] + bias1, 0.f);
            float e2 = fmaxf(c[mt][nt][2] + bias0, 0.f);
            float e3 = fmaxf(c[mt][nt][3] + bias1, 0.f);
            ps0 += (v0 ? e0 : 0.f) + (v1 ? e2 : 0.f);
            ps1 += (v0 ? e1 : 0.f) + (v1 ? e3 : 0.f);
        }
        // reduce over gid (lane bits 2..4)
        #pragma unroll
        for (int d = 4; d < 32; d <<= 1) {
            ps0 += __shfl_xor_sync(0xffffffffu, ps0, d);
            ps1 += __shfl_xor_sync(0xffffffffu, ps1, d);
        }
        if (lane < 4) {
            atomicAdd(&spool[colg], ps0);
            atomicAdd(&spool[colg + 1], ps1);
        }
    }
    __syncthreads();
    if (t < 128) atomicAdd(&g_pool[t], spool[t]);
}

// 8) final head: out = (pool/N) @ Wlin^T + blin
__global__ void k_final(const float* __restrict__ Wlin,
                        const float* __restrict__ blin,
                        float* __restrict__ out) {
    __shared__ float s0[128], s1[128];
    int l = threadIdx.x;  // 128 threads
    float g = g_pool[l] * (1.0f / (float)N_NODES);
    s0[l] = g * Wlin[l];
    s1[l] = g * Wlin[128 + l];
    __syncthreads();
    for (int st = 64; st > 0; st >>= 1) {
        if (l < st) { s0[l] += s0[l + st]; s1[l] += s1[l + st]; }
        __syncthreads();
    }
    if (l == 0) {
        out[0] = s0[0] + blin[0];
        out[1] = s1[0] + blin[1];
    }
}

// ---------------------------------------------------------------------------
extern "C" void kernel_launch(void* const* d_in, const int* in_sizes, int n_in,
                              void* d_out, int out_size) {
    const float* x       = (const float*)d_in[0];
    const int*   ei      = (const int*)  d_in[1];
    const float* W1_rel  = (const float*)d_in[2];
    const float* b1      = (const float*)d_in[3];
    const float* W1_root = (const float*)d_in[4];
    const float* W2_rel  = (const float*)d_in[5];
    const float* b2      = (const float*)d_in[6];
    const float* W2_root = (const float*)d_in[7];
    const float* Wlin    = (const float*)d_in[8];
    const float* blin    = (const float*)d_in[9];
    float* out = (float*)d_out;

    k_init    <<<(N_NODES + 255) / 256, 256>>>();
    k_hist    <<<(N_EDGES + 255) / 256, 256>>>(ei);
    k_scan1   <<<NSCANB, 1024>>>();
    k_scan2   <<<1, 128>>>();
    k_scan3   <<<NSCANB, 1024>>>();
    k_scatter <<<(N_EDGES + 255) / 256, 256>>>(ei);
    k_h1      <<<(N_NODES + 127) / 128, 128>>>(x, W1_rel, b1, W1_root);
    k_agg2    <<<(N_NODES * 32 + 255) / 256, 256>>>();
    k_gemm_mma<<<(N_NODES + 127) / 128, 256>>>(W2_rel, W2_root, b2);
    k_final   <<<1, 128>>>(Wlin, blin, out);
}